// round 13
// baseline (speedup 1.0000x reference)
#include <cuda_runtime.h>
#include <cuda_fp16.h>
#include <math.h>
#include <stdint.h>

// Problem constants
constexpr int kB  = 2;
constexpr int kL  = 2048;
constexpr int kD  = 2048;
constexpr int kH  = 16;
constexpr int kHD = 128;
constexpr int kFF = 8192;
constexpr int kM  = kB * kL;  // 4096 rows

// ---------------------------------------------------------------------------
// Scratch buffers (device globals — no allocation allowed)
// ---------------------------------------------------------------------------
__device__ float  g_x2[(size_t)kM * kD];
__device__ __half g_qkv16[(size_t)kM * 3 * kD];
__device__ __half g_h16[(size_t)kM * kD];
__device__ __half g_attn16[(size_t)kM * kD];
__device__ __half g_act16[(size_t)kM * kFF];
// fp16 weights: [qkv][out][glu (gate/up row-interleaved)][down]
constexpr size_t W_QKV  = 0;
constexpr size_t W_OUT  = (size_t)3 * kD * kD;
constexpr size_t W_GLU  = W_OUT + (size_t)kD * kD;
constexpr size_t W_DOWN = W_GLU + (size_t)2 * kFF * kD;
constexpr size_t W_TOTAL = W_DOWN + (size_t)kD * kFF;
__device__ __half g_w16[W_TOTAL];

extern __shared__ char dynsmem[];

// ---------------------------------------------------------------------------
// PTX helpers
// ---------------------------------------------------------------------------
__device__ __forceinline__ void mma_f16(float* c, const uint32_t* a, const uint32_t* b) {
    asm volatile(
        "mma.sync.aligned.m16n8k16.row.col.f32.f16.f16.f32 "
        "{%0,%1,%2,%3}, {%4,%5,%6,%7}, {%8,%9}, {%0,%1,%2,%3};"
        : "+f"(c[0]), "+f"(c[1]), "+f"(c[2]), "+f"(c[3])
        : "r"(a[0]), "r"(a[1]), "r"(a[2]), "r"(a[3]), "r"(b[0]), "r"(b[1]));
}
__device__ __forceinline__ void ldsm_x4(uint32_t& r0, uint32_t& r1, uint32_t& r2,
                                        uint32_t& r3, uint32_t addr) {
    asm volatile("ldmatrix.sync.aligned.m8n8.x4.shared.b16 {%0,%1,%2,%3}, [%4];"
                 : "=r"(r0), "=r"(r1), "=r"(r2), "=r"(r3) : "r"(addr));
}
__device__ __forceinline__ void ldsm_x4_t(uint32_t& r0, uint32_t& r1, uint32_t& r2,
                                          uint32_t& r3, uint32_t addr) {
    asm volatile("ldmatrix.sync.aligned.m8n8.x4.trans.shared.b16 {%0,%1,%2,%3}, [%4];"
                 : "=r"(r0), "=r"(r1), "=r"(r2), "=r"(r3) : "r"(addr));
}
__device__ __forceinline__ void cp_async16(uint32_t smem_addr, const void* gmem) {
    asm volatile("cp.async.cg.shared.global [%0], [%1], 16;\n"
                 :: "r"(smem_addr), "l"(gmem));
}
__device__ __forceinline__ void cp_commit() {
    asm volatile("cp.async.commit_group;\n" ::: "memory");
}
__device__ __forceinline__ void cp_wait1() {
    asm volatile("cp.async.wait_group 1;\n" ::: "memory");
}
__device__ __forceinline__ uint32_t smem_u32(const void* p) {
    uint32_t a;
    asm("{ .reg .u64 t; cvta.to.shared.u64 t, %1; cvt.u32.u64 %0, t; }"
        : "=r"(a) : "l"(p));
    return a;
}

// ---------------------------------------------------------------------------
// Fused weight convert. gate/up interleaved row-wise into the GLU region.
// ---------------------------------------------------------------------------
constexpr size_t F4R = kD / 4;
constexpr size_t F4_QKV  = W_OUT / 4;
constexpr size_t F4_OUT  = W_GLU / 4;
constexpr size_t F4_GATE = F4_OUT + (size_t)kFF * F4R;
constexpr size_t F4_UP   = F4_GATE + (size_t)kFF * F4R;
constexpr size_t F4_ALL  = W_TOTAL / 4;

__global__ __launch_bounds__(256) void cvt_all_kernel(const float4* __restrict__ qkv_w,
                                                      const float4* __restrict__ out_w,
                                                      const float4* __restrict__ gate_w,
                                                      const float4* __restrict__ up_w,
                                                      const float4* __restrict__ down_w,
                                                      uint2* __restrict__ out) {
    size_t i = (size_t)blockIdx.x * 256 + threadIdx.x;
    const float4* src;
    size_t j, dst;
    if (i < F4_QKV) {
        src = qkv_w; j = i; dst = i;
    } else if (i < F4_OUT) {
        src = out_w; j = i - F4_QKV; dst = i;
    } else if (i < F4_GATE) {
        src = gate_w; j = i - F4_OUT;
        size_t row = j / F4R, col = j % F4R;
        dst = F4_OUT + (2 * row) * F4R + col;
    } else if (i < F4_UP) {
        src = up_w; j = i - F4_GATE;
        size_t row = j / F4R, col = j % F4R;
        dst = F4_OUT + (2 * row + 1) * F4R + col;
    } else {
        src = down_w; j = i - F4_UP; dst = i;
    }
    float4 v = src[j];
    __half2 h0 = __floats2half2_rn(v.x, v.y);
    __half2 h1 = __floats2half2_rn(v.z, v.w);
    out[dst] = make_uint2(*(uint32_t*)&h0, *(uint32_t*)&h1);
}

// ---------------------------------------------------------------------------
// FP16 mma.sync GEMM, 2 CTAs/SM: C[M,N] = A[M,K] @ B[N,K]^T.
// Block 128x128, BK=64, 8 warps each 64x32, 3-stage cp.async pipeline.
// EPI: 0 none, 1 +Aux(fp32), 5 GLU (even=gate, odd=up -> silu(g)*u fp16,
//      paired-lane packed 4B stores).
// ---------------------------------------------------------------------------
constexpr int BM = 128, BN = 128, BK = 64;
constexpr int ROW_W = 36;
constexpr int A_WORDS = BM * ROW_W;
constexpr int B_WORDS = BN * ROW_W;
constexpr int STAGE_WORDS = A_WORDS + B_WORDS;
constexpr int GEMM_SMEM = 3 * STAGE_WORDS * 4;

__device__ __forceinline__ void issue_stage(uint32_t sA, uint32_t sB,
                                            const __half* __restrict__ Ab,
                                            const __half* __restrict__ Bb,
                                            int kt, int Kdim, int tid) {
    const size_t ko = (size_t)kt * BK;
#pragma unroll
    for (int i = 0; i < 4; i++) {
        int idx = tid + 256 * i;
        int row = idx >> 3, ch = idx & 7;
        cp_async16(sA + row * 144 + ch * 16, Ab + (size_t)row * Kdim + ko + ch * 8);
    }
#pragma unroll
    for (int i = 0; i < 4; i++) {
        int idx = tid + 256 * i;
        int row = idx >> 3, ch = idx & 7;
        cp_async16(sB + row * 144 + ch * 16, Bb + (size_t)row * Kdim + ko + ch * 8);
    }
}

template <int EPI, bool OUT16>
__global__ __launch_bounds__(256, 2) void gemm_h(const __half* __restrict__ A,
                                                 const __half* __restrict__ Bm,
                                                 void* __restrict__ Cv,
                                                 const void* __restrict__ AuxV,
                                                 int Ndim, int Kdim) {
    const uint32_t sbase = smem_u32(dynsmem);
    const int tid = threadIdx.x;
    const int wid = tid >> 5, lane = tid & 31;
    const int r = lane >> 2, c = lane & 3;
    const int m0 = blockIdx.y * BM;
    const int n0 = blockIdx.x * BN;
    const int wm = (wid & 1) * 64;
    const int wn = (wid >> 1) * 32;

    const __half* Ab = A + (size_t)m0 * Kdim;
    const __half* Bb = Bm + (size_t)n0 * Kdim;
    const int KT = Kdim / BK;

    const uint32_t a_off = ((wm + (lane & 15)) * ROW_W + (lane >> 4) * 4) * 4;
    const uint32_t b_off = ((wn + ((lane & 16) >> 1) + (lane & 7)) * ROW_W
                            + ((lane >> 3) & 1) * 4) * 4;

    float acc[4][4][4];
#pragma unroll
    for (int mb = 0; mb < 4; mb++)
#pragma unroll
        for (int nb = 0; nb < 4; nb++)
#pragma unroll
            for (int q = 0; q < 4; q++) acc[mb][nb][q] = 0.f;

#pragma unroll
    for (int s = 0; s < 2; s++) {
        uint32_t sA = sbase + s * STAGE_WORDS * 4;
        issue_stage(sA, sA + A_WORDS * 4, Ab, Bb, s, Kdim, tid);
        cp_commit();
    }

    int stage = 0;
    for (int kt = 0; kt < KT; kt++) {
        cp_wait1();
        __syncthreads();
        if (kt + 2 < KT) {
            int fs = stage + 2; if (fs >= 3) fs -= 3;
            uint32_t sA = sbase + fs * STAGE_WORDS * 4;
            issue_stage(sA, sA + A_WORDS * 4, Ab, Bb, kt + 2, Kdim, tid);
        }
        cp_commit();

        const uint32_t sA = sbase + stage * STAGE_WORDS * 4;
        const uint32_t sB = sA + A_WORDS * 4;
#pragma unroll
        for (int ks = 0; ks < 4; ks++) {
            uint32_t af[4][4], bf[4][2];
#pragma unroll
            for (int mb = 0; mb < 4; mb++)
                ldsm_x4(af[mb][0], af[mb][1], af[mb][2], af[mb][3],
                        sA + a_off + mb * (16 * ROW_W * 4) + ks * 32);
#pragma unroll
            for (int nb2 = 0; nb2 < 2; nb2++)
                ldsm_x4(bf[2 * nb2][0], bf[2 * nb2][1], bf[2 * nb2 + 1][0], bf[2 * nb2 + 1][1],
                        sB + b_off + nb2 * (16 * ROW_W * 4) + ks * 32);
#pragma unroll
            for (int mb = 0; mb < 4; mb++)
#pragma unroll
                for (int nb = 0; nb < 4; nb++)
                    mma_f16(acc[mb][nb], af[mb], bf[nb]);
        }
        if (++stage == 3) stage = 0;
    }

    // Epilogue
#pragma unroll
    for (int mb = 0; mb < 4; mb++) {
#pragma unroll
        for (int nb = 0; nb < 4; nb++) {
            int row0 = m0 + wm + mb * 16 + r;
            int col = n0 + wn + nb * 8 + c * 2;
#pragma unroll
            for (int half = 0; half < 2; half++) {
                int row = row0 + half * 8;
                float v0 = acc[mb][nb][half * 2 + 0];
                float v1 = acc[mb][nb][half * 2 + 1];
                if (EPI == 5) {
                    // GLU: v0 = gate (even col), v1 = up (odd col).
                    // Thread's output half sits at col/2 = base + c. Pair lanes
                    // (c even|odd hold adjacent halves) -> 4B packed store.
                    float g = v0 / (1.f + __expf(-v0));
                    __half ho = __float2half(g * v1);
                    uint32_t bits = (uint32_t)*(uint16_t*)&ho;
                    uint32_t nbr = __shfl_xor_sync(0xffffffffu, bits, 1);
                    if ((lane & 1) == 0) {
                        uint32_t packed = bits | (nbr << 16);
                        size_t hoff = (size_t)row * (Ndim / 2) + (col >> 1);
                        *(uint32_t*)((__half*)Cv + hoff) = packed;
                    }
                    continue;
                }
                size_t off = (size_t)row * Ndim + col;
                if (EPI == 1) {
                    float2 a2 = *(const float2*)((const float*)AuxV + off);
                    v0 += a2.x; v1 += a2.y;
                }
                if (OUT16) {
                    __half2 hv = __floats2half2_rn(v0, v1);
                    *(uint32_t*)((__half*)Cv + off) = *(uint32_t*)&hv;
                } else {
                    *(float2*)((float*)Cv + off) = make_float2(v0, v1);
                }
            }
        }
    }
}

// ---------------------------------------------------------------------------
// RMSNorm: one block per row, fp16 output
// ---------------------------------------------------------------------------
__global__ __launch_bounds__(256) void rmsnorm_kernel(const float* __restrict__ x,
                                                      const float* __restrict__ w,
                                                      __half* __restrict__ out) {
    int row = blockIdx.x;
    int t = threadIdx.x;
    const float4* xr = (const float4*)(x + (size_t)row * kD);
    float4 v0 = xr[t];
    float4 v1 = xr[t + 256];
    float s = v0.x * v0.x + v0.y * v0.y + v0.z * v0.z + v0.w * v0.w
            + v1.x * v1.x + v1.y * v1.y + v1.z * v1.z + v1.w * v1.w;
#pragma unroll
    for (int o = 16; o > 0; o >>= 1) s += __shfl_xor_sync(0xffffffffu, s, o);

    __shared__ float red[8];
    __shared__ float rtot;
    int wid = t >> 5, lane = t & 31;
    if (lane == 0) red[wid] = s;
    __syncthreads();
    if (t == 0) {
        float tot = 0.f;
#pragma unroll
        for (int i = 0; i < 8; i++) tot += red[i];
        rtot = rsqrtf(tot * (1.0f / kD) + 1e-6f);
    }
    __syncthreads();
    float r = rtot;

    const float4* wv = (const float4*)w;
    float4 w0 = wv[t], w1 = wv[t + 256];
    __half2 h0 = __floats2half2_rn(v0.x * r * w0.x, v0.y * r * w0.y);
    __half2 h1 = __floats2half2_rn(v0.z * r * w0.z, v0.w * r * w0.w);
    __half2 h2 = __floats2half2_rn(v1.x * r * w1.x, v1.y * r * w1.y);
    __half2 h3 = __floats2half2_rn(v1.z * r * w1.z, v1.w * r * w1.w);
    uint2* ov = (uint2*)(out + (size_t)row * kD);
    ov[t] = make_uint2(*(uint32_t*)&h0, *(uint32_t*)&h1);
    ov[t + 256] = make_uint2(*(uint32_t*)&h2, *(uint32_t*)&h3);
}

// ---------------------------------------------------------------------------
// FA2 tensor-core flash attention. Q fragments hoisted out of the KV loop
// (loaded once into 32 regs). Heaviest q-tiles scheduled first.
// 128 threads / 4 warps; 2 CTAs/SM.
// ---------------------------------------------------------------------------
constexpr int AQ_W = 68;
constexpr int OFF_Q = 0;
constexpr int OFF_K = OFF_Q + 64 * AQ_W;
constexpr int OFF_V = OFF_K + 64 * AQ_W;
constexpr int ATTN_SMEM = (OFF_V + 64 * AQ_W) * 4;   // 52224 bytes

__global__ __launch_bounds__(128, 2) void attn_kernel(const __half* __restrict__ qkv,
                                                      __half* __restrict__ o_out) {
    uint32_t* smw = (uint32_t*)dynsmem;
    const uint32_t sb = smem_u32(smw);
    const int t = threadIdx.x, wid = t >> 5, lane = t & 31;
    const int qt = gridDim.x - 1 - blockIdx.x;      // heaviest tiles first
    const int q0 = qt * 64, h = blockIdx.y, b = blockIdx.z;
    const float scale = 0.08838834764831845f;

    const __half* base = qkv + ((size_t)b * kL) * (3 * kD) + h * kHD;

    // Load Q tile [64][128]
#pragma unroll
    for (int i = 0; i < 8; i++) {
        int idx = t + 128 * i;
        int row = idx >> 4, ch = idx & 15;
        *(uint4*)(smw + OFF_Q + row * AQ_W + ch * 4) =
            *(const uint4*)(base + (size_t)(q0 + row) * (3 * kD) + ch * 8);
    }
    __syncthreads();

    const int wr = wid * 16;
    const int l15 = lane & 15, l7 = lane & 7;
    const uint32_t qa = sb + (OFF_Q + (wr + l15) * AQ_W + (lane >> 4) * 4) * 4;
    const uint32_t ka = sb + (OFF_K + (((lane & 16) >> 1) + l7) * AQ_W
                              + ((lane >> 3) & 1) * 4) * 4;
    const uint32_t va = sb + (OFF_V + ((lane & 8) + l7) * AQ_W) * 4
                        + ((lane & 16) >> 1) * 2;

    // Hoist Q fragments: invariant across KV tiles
    uint32_t qf[8][4];
#pragma unroll
    for (int ks = 0; ks < 8; ks++)
        ldsm_x4(qf[ks][0], qf[ks][1], qf[ks][2], qf[ks][3], qa + ks * 32);

    float oacc[16][4];
#pragma unroll
    for (int nb = 0; nb < 16; nb++)
#pragma unroll
        for (int q = 0; q < 4; q++) oacc[nb][q] = 0.f;

    float m0 = -1e30f, m1 = -1e30f, l0 = 0.f, l1 = 0.f;
    const int rS = wr + (lane >> 2);
    const int c2 = (lane & 3) * 2;
    const int nkb = qt + 1;

    for (int kb = 0; kb < nkb; kb++) {
        const int k0 = kb * 64;
        __syncthreads();  // prior tile's K/V readers done (Q region never rewritten)
#pragma unroll
        for (int i = 0; i < 8; i++) {
            int idx = t + 128 * i;
            int row = idx >> 4, ch = idx & 15;
            const __half* kr = base + (size_t)(k0 + row) * (3 * kD) + kD + ch * 8;
            *(uint4*)(smw + OFF_K + row * AQ_W + ch * 4) = *(const uint4*)(kr);
            *(uint4*)(smw + OFF_V + row * AQ_W + ch * 4) = *(const uint4*)(kr + kD);
        }
        __syncthreads();

        // S = Q @ K^T
        float s[8][4];
#pragma unroll
        for (int j = 0; j < 8; j++)
#pragma unroll
            for (int q = 0; q < 4; q++) s[j][q] = 0.f;
#pragma unroll
        for (int ks = 0; ks < 8; ks++) {
            uint32_t bf[8][2];
#pragma unroll
            for (int nq = 0; nq < 4; nq++)
                ldsm_x4(bf[2 * nq][0], bf[2 * nq][1], bf[2 * nq + 1][0], bf[2 * nq + 1][1],
                        ka + nq * (16 * AQ_W * 4) + ks * 32);
#pragma unroll
            for (int j = 0; j < 8; j++) mma_f16(s[j], qf[ks], bf[j]);
        }

        // Scale + mask + register softmax
        const bool diag = (kb == nkb - 1);
        float mx0 = -1e30f, mx1 = -1e30f;
#pragma unroll
        for (int j = 0; j < 8; j++) {
            int col = k0 + j * 8 + c2;
            s[j][0] *= scale; s[j][1] *= scale;
            s[j][2] *= scale; s[j][3] *= scale;
            if (diag) {
                if (col > q0 + rS) s[j][0] = -1e30f;
                if (col + 1 > q0 + rS) s[j][1] = -1e30f;
                if (col > q0 + rS + 8) s[j][2] = -1e30f;
                if (col + 1 > q0 + rS + 8) s[j][3] = -1e30f;
            }
            mx0 = fmaxf(mx0, fmaxf(s[j][0], s[j][1]));
            mx1 = fmaxf(mx1, fmaxf(s[j][2], s[j][3]));
        }
        mx0 = fmaxf(mx0, __shfl_xor_sync(0xffffffffu, mx0, 1));
        mx0 = fmaxf(mx0, __shfl_xor_sync(0xffffffffu, mx0, 2));
        mx1 = fmaxf(mx1, __shfl_xor_sync(0xffffffffu, mx1, 1));
        mx1 = fmaxf(mx1, __shfl_xor_sync(0xffffffffu, mx1, 2));
        float mn0 = fmaxf(m0, mx0), mn1 = fmaxf(m1, mx1);
        float corr0 = __expf(m0 - mn0), corr1 = __expf(m1 - mn1);

        float sum0 = 0.f, sum1 = 0.f;
        uint32_t pl[8], pu[8];
#pragma unroll
        for (int j = 0; j < 8; j++) {
            float p0 = __expf(s[j][0] - mn0);
            float p1 = __expf(s[j][1] - mn0);
            float p2 = __expf(s[j][2] - mn1);
            float p3 = __expf(s[j][3] - mn1);
            sum0 += p0 + p1; sum1 += p2 + p3;
            __half2 hl = __floats2half2_rn(p0, p1);
            __half2 hu = __floats2half2_rn(p2, p3);
            pl[j] = *(uint32_t*)&hl; pu[j] = *(uint32_t*)&hu;
        }
        sum0 += __shfl_xor_sync(0xffffffffu, sum0, 1);
        sum0 += __shfl_xor_sync(0xffffffffu, sum0, 2);
        sum1 += __shfl_xor_sync(0xffffffffu, sum1, 1);
        sum1 += __shfl_xor_sync(0xffffffffu, sum1, 2);
        l0 = l0 * corr0 + sum0; l1 = l1 * corr1 + sum1;
        m0 = mn0; m1 = mn1;

#pragma unroll
        for (int nb = 0; nb < 16; nb++) {
            oacc[nb][0] *= corr0; oacc[nb][1] *= corr0;
            oacc[nb][2] *= corr1; oacc[nb][3] *= corr1;
        }

        // O += P @ V
#pragma unroll
        for (int kc = 0; kc < 4; kc++) {
            uint32_t af2[4] = { pl[2 * kc], pu[2 * kc], pl[2 * kc + 1], pu[2 * kc + 1] };
            uint32_t bv[16][2];
#pragma unroll
            for (int nb2 = 0; nb2 < 8; nb2++)
                ldsm_x4_t(bv[2 * nb2][0], bv[2 * nb2][1],
                          bv[2 * nb2 + 1][0], bv[2 * nb2 + 1][1],
                          va + kc * (16 * AQ_W * 4) + nb2 * 32);
#pragma unroll
            for (int nb = 0; nb < 16; nb++) mma_f16(oacc[nb], af2, bv[nb]);
        }
    }

    float inv0 = 1.f / l0, inv1 = 1.f / l1;
#pragma unroll
    for (int nb = 0; nb < 16; nb++) {
        int col = nb * 8 + c2;
        __half* d0 = o_out + ((size_t)(b * kL + q0 + rS)) * kD + h * kHD + col;
        __half* d1 = d0 + (size_t)8 * kD;
        __half2 h01 = __floats2half2_rn(oacc[nb][0] * inv0, oacc[nb][1] * inv0);
        __half2 h23 = __floats2half2_rn(oacc[nb][2] * inv1, oacc[nb][3] * inv1);
        *(uint32_t*)d0 = *(uint32_t*)&h01;
        *(uint32_t*)d1 = *(uint32_t*)&h23;
    }
}

// ---------------------------------------------------------------------------
// Launch
// ---------------------------------------------------------------------------
extern "C" void kernel_launch(void* const* d_in, const int* in_sizes, int n_in,
                              void* d_out, int out_size) {
    (void)in_sizes; (void)n_in; (void)out_size;
    const float* x       = (const float*)d_in[0];
    const float* norm1_w = (const float*)d_in[2];
    const float* qkv_w   = (const float*)d_in[3];
    const float* out_w   = (const float*)d_in[4];
    const float* norm2_w = (const float*)d_in[5];
    const float* gate_w  = (const float*)d_in[6];
    const float* up_w    = (const float*)d_in[7];
    const float* down_w  = (const float*)d_in[8];
    float* out = (float*)d_out;

    float* x2;
    __half *qkv16, *h16, *attn16, *act16, *w16;
    cudaGetSymbolAddress((void**)&x2, g_x2);
    cudaGetSymbolAddress((void**)&qkv16, g_qkv16);
    cudaGetSymbolAddress((void**)&h16, g_h16);
    cudaGetSymbolAddress((void**)&attn16, g_attn16);
    cudaGetSymbolAddress((void**)&act16, g_act16);
    cudaGetSymbolAddress((void**)&w16, g_w16);

    cudaFuncSetAttribute((const void*)attn_kernel,
                         cudaFuncAttributeMaxDynamicSharedMemorySize, ATTN_SMEM);
    cudaFuncSetAttribute((const void*)gemm_h<0, true>,
                         cudaFuncAttributeMaxDynamicSharedMemorySize, GEMM_SMEM);
    cudaFuncSetAttribute((const void*)gemm_h<1, false>,
                         cudaFuncAttributeMaxDynamicSharedMemorySize, GEMM_SMEM);
    cudaFuncSetAttribute((const void*)gemm_h<5, true>,
                         cudaFuncAttributeMaxDynamicSharedMemorySize, GEMM_SMEM);

    // 0) Convert all weights to fp16 (gate/up interleaved into GLU region)
    cvt_all_kernel<<<(int)(F4_ALL / 256), 256>>>(
        (const float4*)qkv_w, (const float4*)out_w, (const float4*)gate_w,
        (const float4*)up_w, (const float4*)down_w, (uint2*)w16);

    // 1) h16 = rmsnorm(x, norm1_w)
    rmsnorm_kernel<<<kM, 256>>>(x, norm1_w, h16);
    // 2) qkv16 = h16 @ qkv_w16^T
    gemm_h<0, true><<<dim3(3 * kD / BN, kM / BM), 256, GEMM_SMEM>>>(
        h16, w16 + W_QKV, qkv16, nullptr, 3 * kD, kD);
    // 3) FA2 tensor-core attention
    attn_kernel<<<dim3(kL / 64, kH, kB), 128, ATTN_SMEM>>>(qkv16, attn16);
    // 4) x2 = attn16 @ out_w16^T + x
    gemm_h<1, false><<<dim3(kD / BN, kM / BM), 256, GEMM_SMEM>>>(
        attn16, w16 + W_OUT, x2, x, kD, kD);
    // 5) h16 = rmsnorm(x2, norm2_w)
    rmsnorm_kernel<<<kM, 256>>>(x2, norm2_w, h16);
    // 6) act16 = silu(h16 @ gate^T) * (h16 @ up^T)  — fused GLU GEMM
    gemm_h<5, true><<<dim3(2 * kFF / BN, kM / BM), 256, GEMM_SMEM>>>(
        h16, w16 + W_GLU, act16, nullptr, 2 * kFF, kD);
    // 7) out = act16 @ down_w16^T + x2
    gemm_h<1, false><<<dim3(kD / BN, kM / BM), 256, GEMM_SMEM>>>(
        act16, w16 + W_DOWN, out, x2, kD, kFF);
}

// round 14
// speedup vs baseline: 1.0206x; 1.0206x over previous
#include <cuda_runtime.h>
#include <cuda_fp16.h>
#include <math.h>
#include <stdint.h>

// Problem constants
constexpr int kB  = 2;
constexpr int kL  = 2048;
constexpr int kD  = 2048;
constexpr int kH  = 16;
constexpr int kHD = 128;
constexpr int kFF = 8192;
constexpr int kM  = kB * kL;  // 4096 rows

// ---------------------------------------------------------------------------
// Scratch buffers (device globals — no allocation allowed)
// ---------------------------------------------------------------------------
__device__ float  g_x2[(size_t)kM * kD];
__device__ __half g_qkv16[(size_t)kM * 3 * kD];
__device__ __half g_h16[(size_t)kM * kD];
__device__ __half g_attn16[(size_t)kM * kD];
__device__ __half g_act16[(size_t)kM * kFF];
// fp16 weights: [qkv][out][glu (gate/up row-interleaved)][down]
constexpr size_t W_QKV  = 0;
constexpr size_t W_OUT  = (size_t)3 * kD * kD;
constexpr size_t W_GLU  = W_OUT + (size_t)kD * kD;
constexpr size_t W_DOWN = W_GLU + (size_t)2 * kFF * kD;
constexpr size_t W_TOTAL = W_DOWN + (size_t)kD * kFF;
__device__ __half g_w16[W_TOTAL];

extern __shared__ char dynsmem[];

// ---------------------------------------------------------------------------
// PTX helpers
// ---------------------------------------------------------------------------
__device__ __forceinline__ void mma_f16(float* c, const uint32_t* a, const uint32_t* b) {
    asm volatile(
        "mma.sync.aligned.m16n8k16.row.col.f32.f16.f16.f32 "
        "{%0,%1,%2,%3}, {%4,%5,%6,%7}, {%8,%9}, {%0,%1,%2,%3};"
        : "+f"(c[0]), "+f"(c[1]), "+f"(c[2]), "+f"(c[3])
        : "r"(a[0]), "r"(a[1]), "r"(a[2]), "r"(a[3]), "r"(b[0]), "r"(b[1]));
}
__device__ __forceinline__ void ldsm_x4(uint32_t& r0, uint32_t& r1, uint32_t& r2,
                                        uint32_t& r3, uint32_t addr) {
    asm volatile("ldmatrix.sync.aligned.m8n8.x4.shared.b16 {%0,%1,%2,%3}, [%4];"
                 : "=r"(r0), "=r"(r1), "=r"(r2), "=r"(r3) : "r"(addr));
}
__device__ __forceinline__ void ldsm_x4_t(uint32_t& r0, uint32_t& r1, uint32_t& r2,
                                          uint32_t& r3, uint32_t addr) {
    asm volatile("ldmatrix.sync.aligned.m8n8.x4.trans.shared.b16 {%0,%1,%2,%3}, [%4];"
                 : "=r"(r0), "=r"(r1), "=r"(r2), "=r"(r3) : "r"(addr));
}
__device__ __forceinline__ void cp_async16(uint32_t smem_addr, const void* gmem) {
    asm volatile("cp.async.cg.shared.global [%0], [%1], 16;\n"
                 :: "r"(smem_addr), "l"(gmem));
}
__device__ __forceinline__ void cp_commit() {
    asm volatile("cp.async.commit_group;\n" ::: "memory");
}
__device__ __forceinline__ void cp_wait0() {
    asm volatile("cp.async.wait_group 0;\n" ::: "memory");
}
__device__ __forceinline__ void cp_wait1() {
    asm volatile("cp.async.wait_group 1;\n" ::: "memory");
}
__device__ __forceinline__ uint32_t smem_u32(const void* p) {
    uint32_t a;
    asm("{ .reg .u64 t; cvta.to.shared.u64 t, %1; cvt.u32.u64 %0, t; }"
        : "=r"(a) : "l"(p));
    return a;
}

// ---------------------------------------------------------------------------
// Fused weight convert. gate/up interleaved row-wise into the GLU region.
// ---------------------------------------------------------------------------
constexpr size_t F4R = kD / 4;
constexpr size_t F4_QKV  = W_OUT / 4;
constexpr size_t F4_OUT  = W_GLU / 4;
constexpr size_t F4_GATE = F4_OUT + (size_t)kFF * F4R;
constexpr size_t F4_UP   = F4_GATE + (size_t)kFF * F4R;
constexpr size_t F4_ALL  = W_TOTAL / 4;

__global__ __launch_bounds__(256) void cvt_all_kernel(const float4* __restrict__ qkv_w,
                                                      const float4* __restrict__ out_w,
                                                      const float4* __restrict__ gate_w,
                                                      const float4* __restrict__ up_w,
                                                      const float4* __restrict__ down_w,
                                                      uint2* __restrict__ out) {
    size_t i = (size_t)blockIdx.x * 256 + threadIdx.x;
    const float4* src;
    size_t j, dst;
    if (i < F4_QKV) {
        src = qkv_w; j = i; dst = i;
    } else if (i < F4_OUT) {
        src = out_w; j = i - F4_QKV; dst = i;
    } else if (i < F4_GATE) {
        src = gate_w; j = i - F4_OUT;
        size_t row = j / F4R, col = j % F4R;
        dst = F4_OUT + (2 * row) * F4R + col;
    } else if (i < F4_UP) {
        src = up_w; j = i - F4_GATE;
        size_t row = j / F4R, col = j % F4R;
        dst = F4_OUT + (2 * row + 1) * F4R + col;
    } else {
        src = down_w; j = i - F4_UP; dst = i;
    }
    float4 v = src[j];
    __half2 h0 = __floats2half2_rn(v.x, v.y);
    __half2 h1 = __floats2half2_rn(v.z, v.w);
    out[dst] = make_uint2(*(uint32_t*)&h0, *(uint32_t*)&h1);
}

// ---------------------------------------------------------------------------
// FP16 mma.sync GEMM, 2 CTAs/SM (round-12 proven config).
// EPI: 0 none, 1 +Aux(fp32), 5 GLU (even=gate, odd=up -> silu(g)*u, scalar
// fp16 store at col/2).
// ---------------------------------------------------------------------------
constexpr int BM = 128, BN = 128, BK = 64;
constexpr int ROW_W = 36;
constexpr int A_WORDS = BM * ROW_W;
constexpr int B_WORDS = BN * ROW_W;
constexpr int STAGE_WORDS = A_WORDS + B_WORDS;
constexpr int GEMM_SMEM = 3 * STAGE_WORDS * 4;

__device__ __forceinline__ void issue_stage(uint32_t sA, uint32_t sB,
                                            const __half* __restrict__ Ab,
                                            const __half* __restrict__ Bb,
                                            int kt, int Kdim, int tid) {
    const size_t ko = (size_t)kt * BK;
#pragma unroll
    for (int i = 0; i < 4; i++) {
        int idx = tid + 256 * i;
        int row = idx >> 3, ch = idx & 7;
        cp_async16(sA + row * 144 + ch * 16, Ab + (size_t)row * Kdim + ko + ch * 8);
    }
#pragma unroll
    for (int i = 0; i < 4; i++) {
        int idx = tid + 256 * i;
        int row = idx >> 3, ch = idx & 7;
        cp_async16(sB + row * 144 + ch * 16, Bb + (size_t)row * Kdim + ko + ch * 8);
    }
}

template <int EPI, bool OUT16>
__global__ __launch_bounds__(256, 2) void gemm_h(const __half* __restrict__ A,
                                                 const __half* __restrict__ Bm,
                                                 void* __restrict__ Cv,
                                                 const void* __restrict__ AuxV,
                                                 int Ndim, int Kdim) {
    const uint32_t sbase = smem_u32(dynsmem);
    const int tid = threadIdx.x;
    const int wid = tid >> 5, lane = tid & 31;
    const int r = lane >> 2, c = lane & 3;
    const int m0 = blockIdx.y * BM;
    const int n0 = blockIdx.x * BN;
    const int wm = (wid & 1) * 64;
    const int wn = (wid >> 1) * 32;

    const __half* Ab = A + (size_t)m0 * Kdim;
    const __half* Bb = Bm + (size_t)n0 * Kdim;
    const int KT = Kdim / BK;

    const uint32_t a_off = ((wm + (lane & 15)) * ROW_W + (lane >> 4) * 4) * 4;
    const uint32_t b_off = ((wn + ((lane & 16) >> 1) + (lane & 7)) * ROW_W
                            + ((lane >> 3) & 1) * 4) * 4;

    float acc[4][4][4];
#pragma unroll
    for (int mb = 0; mb < 4; mb++)
#pragma unroll
        for (int nb = 0; nb < 4; nb++)
#pragma unroll
            for (int q = 0; q < 4; q++) acc[mb][nb][q] = 0.f;

#pragma unroll
    for (int s = 0; s < 2; s++) {
        uint32_t sA = sbase + s * STAGE_WORDS * 4;
        issue_stage(sA, sA + A_WORDS * 4, Ab, Bb, s, Kdim, tid);
        cp_commit();
    }

    int stage = 0;
    for (int kt = 0; kt < KT; kt++) {
        cp_wait1();
        __syncthreads();
        if (kt + 2 < KT) {
            int fs = stage + 2; if (fs >= 3) fs -= 3;
            uint32_t sA = sbase + fs * STAGE_WORDS * 4;
            issue_stage(sA, sA + A_WORDS * 4, Ab, Bb, kt + 2, Kdim, tid);
        }
        cp_commit();

        const uint32_t sA = sbase + stage * STAGE_WORDS * 4;
        const uint32_t sB = sA + A_WORDS * 4;
#pragma unroll
        for (int ks = 0; ks < 4; ks++) {
            uint32_t af[4][4], bf[4][2];
#pragma unroll
            for (int mb = 0; mb < 4; mb++)
                ldsm_x4(af[mb][0], af[mb][1], af[mb][2], af[mb][3],
                        sA + a_off + mb * (16 * ROW_W * 4) + ks * 32);
#pragma unroll
            for (int nb2 = 0; nb2 < 2; nb2++)
                ldsm_x4(bf[2 * nb2][0], bf[2 * nb2][1], bf[2 * nb2 + 1][0], bf[2 * nb2 + 1][1],
                        sB + b_off + nb2 * (16 * ROW_W * 4) + ks * 32);
#pragma unroll
            for (int mb = 0; mb < 4; mb++)
#pragma unroll
                for (int nb = 0; nb < 4; nb++)
                    mma_f16(acc[mb][nb], af[mb], bf[nb]);
        }
        if (++stage == 3) stage = 0;
    }

    // Epilogue
#pragma unroll
    for (int mb = 0; mb < 4; mb++) {
#pragma unroll
        for (int nb = 0; nb < 4; nb++) {
            int row0 = m0 + wm + mb * 16 + r;
            int col = n0 + wn + nb * 8 + c * 2;
#pragma unroll
            for (int half = 0; half < 2; half++) {
                int row = row0 + half * 8;
                float v0 = acc[mb][nb][half * 2 + 0];
                float v1 = acc[mb][nb][half * 2 + 1];
                if (EPI == 5) {
                    float g = v0 / (1.f + __expf(-v0));
                    __half* dst = (__half*)Cv + (size_t)row * (Ndim / 2) + (col >> 1);
                    *dst = __float2half(g * v1);
                    continue;
                }
                size_t off = (size_t)row * Ndim + col;
                if (EPI == 1) {
                    float2 a2 = *(const float2*)((const float*)AuxV + off);
                    v0 += a2.x; v1 += a2.y;
                }
                if (OUT16) {
                    __half2 hv = __floats2half2_rn(v0, v1);
                    *(uint32_t*)((__half*)Cv + off) = *(uint32_t*)&hv;
                } else {
                    *(float2*)((float*)Cv + off) = make_float2(v0, v1);
                }
            }
        }
    }
}

// ---------------------------------------------------------------------------
// RMSNorm: one block per row, fp16 output
// ---------------------------------------------------------------------------
__global__ __launch_bounds__(256) void rmsnorm_kernel(const float* __restrict__ x,
                                                      const float* __restrict__ w,
                                                      __half* __restrict__ out) {
    int row = blockIdx.x;
    int t = threadIdx.x;
    const float4* xr = (const float4*)(x + (size_t)row * kD);
    float4 v0 = xr[t];
    float4 v1 = xr[t + 256];
    float s = v0.x * v0.x + v0.y * v0.y + v0.z * v0.z + v0.w * v0.w
            + v1.x * v1.x + v1.y * v1.y + v1.z * v1.z + v1.w * v1.w;
#pragma unroll
    for (int o = 16; o > 0; o >>= 1) s += __shfl_xor_sync(0xffffffffu, s, o);

    __shared__ float red[8];
    __shared__ float rtot;
    int wid = t >> 5, lane = t & 31;
    if (lane == 0) red[wid] = s;
    __syncthreads();
    if (t == 0) {
        float tot = 0.f;
#pragma unroll
        for (int i = 0; i < 8; i++) tot += red[i];
        rtot = rsqrtf(tot * (1.0f / kD) + 1e-6f);
    }
    __syncthreads();
    float r = rtot;

    const float4* wv = (const float4*)w;
    float4 w0 = wv[t], w1 = wv[t + 256];
    __half2 h0 = __floats2half2_rn(v0.x * r * w0.x, v0.y * r * w0.y);
    __half2 h1 = __floats2half2_rn(v0.z * r * w0.z, v0.w * r * w0.w);
    __half2 h2 = __floats2half2_rn(v1.x * r * w1.x, v1.y * r * w1.y);
    __half2 h3 = __floats2half2_rn(v1.z * r * w1.z, v1.w * r * w1.w);
    uint2* ov = (uint2*)(out + (size_t)row * kD);
    ov[t] = make_uint2(*(uint32_t*)&h0, *(uint32_t*)&h1);
    ov[t + 256] = make_uint2(*(uint32_t*)&h2, *(uint32_t*)&h3);
}

// ---------------------------------------------------------------------------
// FA2 attention with cp.async double-buffered K/V (the single new change).
// Q fragments hoisted (32 regs). Heaviest q-tiles first. 128 thr / 4 warps,
// 2 CTAs/SM (87 KB SMEM).
// ---------------------------------------------------------------------------
constexpr int AQ_W = 68;                        // words per row (272 B)
constexpr int OFF_Q = 0;
constexpr int KV_WORDS = 2 * 64 * AQ_W;         // K+V per stage
constexpr int OFF_KV = 64 * AQ_W;               // stage 0 base
constexpr int ATTN_SMEM = (64 * AQ_W + 2 * KV_WORDS) * 4;  // 87040 bytes

__device__ __forceinline__ void issue_kv(uint32_t sb, int stage,
                                         const __half* __restrict__ base,
                                         int k0, int t) {
    const uint32_t kb = sb + (OFF_KV + stage * KV_WORDS) * 4;
    const uint32_t vb = kb + 64 * AQ_W * 4;
#pragma unroll
    for (int i = 0; i < 8; i++) {
        int idx = t + 128 * i;
        int row = idx >> 4, ch = idx & 15;
        const __half* src = base + (size_t)(k0 + row) * (3 * kD) + kD + ch * 8;
        cp_async16(kb + row * 272 + ch * 16, src);
        cp_async16(vb + row * 272 + ch * 16, src + kD);
    }
}

__global__ __launch_bounds__(128, 2) void attn_kernel(const __half* __restrict__ qkv,
                                                      __half* __restrict__ o_out) {
    uint32_t* smw = (uint32_t*)dynsmem;
    const uint32_t sb = smem_u32(smw);
    const int t = threadIdx.x, wid = t >> 5, lane = t & 31;
    const int qt = gridDim.x - 1 - blockIdx.x;      // heaviest tiles first
    const int q0 = qt * 64, h = blockIdx.y, b = blockIdx.z;
    const float scale = 0.08838834764831845f;

    const __half* base = qkv + ((size_t)b * kL) * (3 * kD) + h * kHD;
    const int nkb = qt + 1;

    // Prologue: async-load Q + KV tile 0 (group 0), then KV tile 1 (group 1)
#pragma unroll
    for (int i = 0; i < 8; i++) {
        int idx = t + 128 * i;
        int row = idx >> 4, ch = idx & 15;
        cp_async16(sb + (OFF_Q + row * AQ_W + ch * 4) * 4,
                   base + (size_t)(q0 + row) * (3 * kD) + ch * 8);
    }
    issue_kv(sb, 0, base, 0, t);
    cp_commit();
    if (nkb > 1) { issue_kv(sb, 1, base, 64, t); }
    cp_commit();

    cp_wait1();          // Q + KV0 arrived (KV1 may still be in flight)
    __syncthreads();

    const int wr = wid * 16;
    const int l15 = lane & 15, l7 = lane & 7;
    const uint32_t qa = sb + (OFF_Q + (wr + l15) * AQ_W + (lane >> 4) * 4) * 4;
    const uint32_t k_lane = ((((lane & 16) >> 1) + l7) * AQ_W + ((lane >> 3) & 1) * 4) * 4;
    const uint32_t v_lane = (((lane & 8) + l7) * AQ_W) * 4 + ((lane & 16) >> 1) * 2;

    // Hoisted Q fragments
    uint32_t qf[8][4];
#pragma unroll
    for (int ks = 0; ks < 8; ks++)
        ldsm_x4(qf[ks][0], qf[ks][1], qf[ks][2], qf[ks][3], qa + ks * 32);

    float oacc[16][4];
#pragma unroll
    for (int nb = 0; nb < 16; nb++)
#pragma unroll
        for (int q = 0; q < 4; q++) oacc[nb][q] = 0.f;

    float m0 = -1e30f, m1 = -1e30f, l0 = 0.f, l1 = 0.f;
    const int rS = wr + (lane >> 2);
    const int c2 = (lane & 3) * 2;

    for (int kb = 0; kb < nkb; kb++) {
        const int k0 = kb * 64;
        const uint32_t ka = sb + (OFF_KV + (kb & 1) * KV_WORDS) * 4 + k_lane;
        const uint32_t va = sb + (OFF_KV + (kb & 1) * KV_WORDS + 64 * AQ_W) * 4 + v_lane;

        // S = Q @ K^T
        float s[8][4];
#pragma unroll
        for (int j = 0; j < 8; j++)
#pragma unroll
            for (int q = 0; q < 4; q++) s[j][q] = 0.f;
#pragma unroll
        for (int ks = 0; ks < 8; ks++) {
            uint32_t bf[8][2];
#pragma unroll
            for (int nq = 0; nq < 4; nq++)
                ldsm_x4(bf[2 * nq][0], bf[2 * nq][1], bf[2 * nq + 1][0], bf[2 * nq + 1][1],
                        ka + nq * (16 * AQ_W * 4) + ks * 32);
#pragma unroll
            for (int j = 0; j < 8; j++) mma_f16(s[j], qf[ks], bf[j]);
        }

        // Scale + mask + register softmax
        const bool diag = (kb == nkb - 1);
        float mx0 = -1e30f, mx1 = -1e30f;
#pragma unroll
        for (int j = 0; j < 8; j++) {
            int col = k0 + j * 8 + c2;
            s[j][0] *= scale; s[j][1] *= scale;
            s[j][2] *= scale; s[j][3] *= scale;
            if (diag) {
                if (col > q0 + rS) s[j][0] = -1e30f;
                if (col + 1 > q0 + rS) s[j][1] = -1e30f;
                if (col > q0 + rS + 8) s[j][2] = -1e30f;
                if (col + 1 > q0 + rS + 8) s[j][3] = -1e30f;
            }
            mx0 = fmaxf(mx0, fmaxf(s[j][0], s[j][1]));
            mx1 = fmaxf(mx1, fmaxf(s[j][2], s[j][3]));
        }
        mx0 = fmaxf(mx0, __shfl_xor_sync(0xffffffffu, mx0, 1));
        mx0 = fmaxf(mx0, __shfl_xor_sync(0xffffffffu, mx0, 2));
        mx1 = fmaxf(mx1, __shfl_xor_sync(0xffffffffu, mx1, 1));
        mx1 = fmaxf(mx1, __shfl_xor_sync(0xffffffffu, mx1, 2));
        float mn0 = fmaxf(m0, mx0), mn1 = fmaxf(m1, mx1);
        float corr0 = __expf(m0 - mn0), corr1 = __expf(m1 - mn1);

        float sum0 = 0.f, sum1 = 0.f;
        uint32_t pl[8], pu[8];
#pragma unroll
        for (int j = 0; j < 8; j++) {
            float p0 = __expf(s[j][0] - mn0);
            float p1 = __expf(s[j][1] - mn0);
            float p2 = __expf(s[j][2] - mn1);
            float p3 = __expf(s[j][3] - mn1);
            sum0 += p0 + p1; sum1 += p2 + p3;
            __half2 hl = __floats2half2_rn(p0, p1);
            __half2 hu = __floats2half2_rn(p2, p3);
            pl[j] = *(uint32_t*)&hl; pu[j] = *(uint32_t*)&hu;
        }
        sum0 += __shfl_xor_sync(0xffffffffu, sum0, 1);
        sum0 += __shfl_xor_sync(0xffffffffu, sum0, 2);
        sum1 += __shfl_xor_sync(0xffffffffu, sum1, 1);
        sum1 += __shfl_xor_sync(0xffffffffu, sum1, 2);
        l0 = l0 * corr0 + sum0; l1 = l1 * corr1 + sum1;
        m0 = mn0; m1 = mn1;

#pragma unroll
        for (int nb = 0; nb < 16; nb++) {
            oacc[nb][0] *= corr0; oacc[nb][1] *= corr0;
            oacc[nb][2] *= corr1; oacc[nb][3] *= corr1;
        }

        // O += P @ V
#pragma unroll
        for (int kc = 0; kc < 4; kc++) {
            uint32_t af2[4] = { pl[2 * kc], pu[2 * kc], pl[2 * kc + 1], pu[2 * kc + 1] };
            uint32_t bv[16][2];
#pragma unroll
            for (int nb2 = 0; nb2 < 8; nb2++)
                ldsm_x4_t(bv[2 * nb2][0], bv[2 * nb2][1],
                          bv[2 * nb2 + 1][0], bv[2 * nb2 + 1][1],
                          va + kc * (16 * AQ_W * 4) + nb2 * 32);
#pragma unroll
            for (int nb = 0; nb < 16; nb++) mma_f16(oacc[nb], af2, bv[nb]);
        }

        // Pipeline: wait for tile kb+1, then prefetch tile kb+2 into buf kb&1
        if (kb + 1 < nkb) {
            cp_wait0();
            __syncthreads();     // all warps done reading buf kb&1; KV(kb+1) ready
            if (kb + 2 < nkb) issue_kv(sb, kb & 1, base, (kb + 2) * 64, t);
            cp_commit();
        }
    }

    // Epilogue
    float inv0 = 1.f / l0, inv1 = 1.f / l1;
#pragma unroll
    for (int nb = 0; nb < 16; nb++) {
        int col = nb * 8 + c2;
        __half* d0 = o_out + ((size_t)(b * kL + q0 + rS)) * kD + h * kHD + col;
        __half* d1 = d0 + (size_t)8 * kD;
        __half2 h01 = __floats2half2_rn(oacc[nb][0] * inv0, oacc[nb][1] * inv0);
        __half2 h23 = __floats2half2_rn(oacc[nb][2] * inv1, oacc[nb][3] * inv1);
        *(uint32_t*)d0 = *(uint32_t*)&h01;
        *(uint32_t*)d1 = *(uint32_t*)&h23;
    }
}

// ---------------------------------------------------------------------------
// Launch
// ---------------------------------------------------------------------------
extern "C" void kernel_launch(void* const* d_in, const int* in_sizes, int n_in,
                              void* d_out, int out_size) {
    (void)in_sizes; (void)n_in; (void)out_size;
    const float* x       = (const float*)d_in[0];
    const float* norm1_w = (const float*)d_in[2];
    const float* qkv_w   = (const float*)d_in[3];
    const float* out_w   = (const float*)d_in[4];
    const float* norm2_w = (const float*)d_in[5];
    const float* gate_w  = (const float*)d_in[6];
    const float* up_w    = (const float*)d_in[7];
    const float* down_w  = (const float*)d_in[8];
    float* out = (float*)d_out;

    float* x2;
    __half *qkv16, *h16, *attn16, *act16, *w16;
    cudaGetSymbolAddress((void**)&x2, g_x2);
    cudaGetSymbolAddress((void**)&qkv16, g_qkv16);
    cudaGetSymbolAddress((void**)&h16, g_h16);
    cudaGetSymbolAddress((void**)&attn16, g_attn16);
    cudaGetSymbolAddress((void**)&act16, g_act16);
    cudaGetSymbolAddress((void**)&w16, g_w16);

    cudaFuncSetAttribute((const void*)attn_kernel,
                         cudaFuncAttributeMaxDynamicSharedMemorySize, ATTN_SMEM);
    cudaFuncSetAttribute((const void*)gemm_h<0, true>,
                         cudaFuncAttributeMaxDynamicSharedMemorySize, GEMM_SMEM);
    cudaFuncSetAttribute((const void*)gemm_h<1, false>,
                         cudaFuncAttributeMaxDynamicSharedMemorySize, GEMM_SMEM);
    cudaFuncSetAttribute((const void*)gemm_h<5, true>,
                         cudaFuncAttributeMaxDynamicSharedMemorySize, GEMM_SMEM);

    // 0) Convert all weights to fp16 (gate/up interleaved into GLU region)
    cvt_all_kernel<<<(int)(F4_ALL / 256), 256>>>(
        (const float4*)qkv_w, (const float4*)out_w, (const float4*)gate_w,
        (const float4*)up_w, (const float4*)down_w, (uint2*)w16);

    // 1) h16 = rmsnorm(x, norm1_w)
    rmsnorm_kernel<<<kM, 256>>>(x, norm1_w, h16);
    // 2) qkv16 = h16 @ qkv_w16^T
    gemm_h<0, true><<<dim3(3 * kD / BN, kM / BM), 256, GEMM_SMEM>>>(
        h16, w16 + W_QKV, qkv16, nullptr, 3 * kD, kD);
    // 3) FA2 tensor-core attention (cp.async double-buffered KV)
    attn_kernel<<<dim3(kL / 64, kH, kB), 128, ATTN_SMEM>>>(qkv16, attn16);
    // 4) x2 = attn16 @ out_w16^T + x
    gemm_h<1, false><<<dim3(kD / BN, kM / BM), 256, GEMM_SMEM>>>(
        attn16, w16 + W_OUT, x2, x, kD, kD);
    // 5) h16 = rmsnorm(x2, norm2_w)
    rmsnorm_kernel<<<kM, 256>>>(x2, norm2_w, h16);
    // 6) act16 = silu(h16 @ gate^T) * (h16 @ up^T)  — fused GLU GEMM
    gemm_h<5, true><<<dim3(2 * kFF / BN, kM / BM), 256, GEMM_SMEM>>>(
        h16, w16 + W_GLU, act16, nullptr, 2 * kFF, kD);
    // 7) out = act16 @ down_w16^T + x2
    gemm_h<1, false><<<dim3(kD / BN, kM / BM), 256, GEMM_SMEM>>>(
        act16, w16 + W_DOWN, out, x2, kD, kFF);
}